// round 2
// baseline (speedup 1.0000x reference)
#include <cuda_runtime.h>
#include <cuda_bf16.h>
#include <math.h>

#define B_ROWS 2048
#define C_COLS 32000
#define TPB 256
#define ROWS_PER_CTA 2
#define GRID (B_ROWS / ROWS_PER_CTA)   // 1024 CTAs -> single wave on 148 SMs @ 8 CTA/SM

__device__ float g_row_loss[B_ROWS];
__device__ unsigned int g_done;        // zero-init at load; last CTA resets to 0 each run

// H(n): exact for small n, asymptotic otherwise (err < 1e-9, tolerance is 1e-3).
__device__ __forceinline__ float harmonic(int n) {
    if (n <= 0) return 0.0f;
    if (n < 32) {
        float h = 0.0f;
        #pragma unroll 1
        for (int i = 1; i <= n; ++i) h += 1.0f / (float)i;
        return h;
    }
    const float gamma = 0.57721566490153286f;
    float x = (float)n;
    float inv = 1.0f / x;
    float inv2 = inv * inv;
    return logf(x) + gamma + 0.5f * inv - (1.0f / 12.0f) * inv2
           + (1.0f / 120.0f) * inv2 * inv2;
}

__global__ void __launch_bounds__(TPB) fused_kernel(const float* __restrict__ scores,
                                                    const int* __restrict__ targets,
                                                    float* __restrict__ out) {
    __shared__ float s_hs[TPB / 32];
    __shared__ int   s_cnt[TPB / 32];
    __shared__ bool  s_last;

    const int wid = threadIdx.x >> 5;
    const int lid = threadIdx.x & 31;

    #pragma unroll 1
    for (int r = 0; r < ROWS_PER_CTA; ++r) {
        const int b = blockIdx.x * ROWS_PER_CTA + r;
        const float* row = scores + (size_t)b * C_COLS;
        const int t = targets[b];
        const float gt = __ldg(row + t);          // same address -> L1 broadcast

        const float4* row4 = reinterpret_cast<const float4*>(row);
        const int n4 = C_COLS / 4;                // 8000

        float hs = 0.0f;
        int cnt = 0;
        #pragma unroll 4
        for (int i = threadIdx.x; i < n4; i += TPB) {
            float4 v = row4[i];
            cnt += (v.x > gt) + (v.y > gt) + (v.z > gt) + (v.w > gt);
            hs += fmaxf(v.x - gt + 1.0f, 0.0f);
            hs += fmaxf(v.y - gt + 1.0f, 0.0f);
            hs += fmaxf(v.z - gt + 1.0f, 0.0f);
            hs += fmaxf(v.w - gt + 1.0f, 0.0f);
        }

        #pragma unroll
        for (int off = 16; off > 0; off >>= 1) {
            hs  += __shfl_down_sync(0xFFFFFFFFu, hs,  off);
            cnt += __shfl_down_sync(0xFFFFFFFFu, cnt, off);
        }
        if (lid == 0) { s_hs[wid] = hs; s_cnt[wid] = cnt; }
        __syncthreads();

        if (threadIdx.x == 0) {
            float hsum = 0.0f;
            int   csum = 0;
            #pragma unroll
            for (int w = 0; w < TPB / 32; ++w) { hsum += s_hs[w]; csum += s_cnt[w]; }
            // target itself contributed relu(1) = 1 to hsum; remove it.
            float hinge = hsum - 1.0f;
            int rank = csum;                       // #(scores > gt)
            float weight = (rank == 0) ? 0.0f : harmonic(rank) / (float)rank;
            g_row_loss[b] = weight * hinge;
        }
        __syncthreads();   // protect s_hs/s_cnt reuse for next row
    }

    // ---- last-CTA deterministic final reduction ----
    if (threadIdx.x == 0) {
        __threadfence();                           // make g_row_loss visible
        unsigned int n = atomicAdd(&g_done, 1u);
        s_last = (n == GRID - 1);
    }
    __syncthreads();

    if (s_last) {
        __shared__ float s_red[TPB];
        float acc = 0.0f;
        #pragma unroll
        for (int i = threadIdx.x; i < B_ROWS; i += TPB) acc += g_row_loss[i];
        s_red[threadIdx.x] = acc;
        __syncthreads();
        #pragma unroll
        for (int off = TPB / 2; off > 0; off >>= 1) {
            if (threadIdx.x < off) s_red[threadIdx.x] += s_red[threadIdx.x + off];
            __syncthreads();
        }
        if (threadIdx.x == 0) {
            out[0] = s_red[0] / (float)B_ROWS;
            g_done = 0;                            // reset for next graph replay
        }
    }
}

extern "C" void kernel_launch(void* const* d_in, const int* in_sizes, int n_in,
                              void* d_out, int out_size) {
    const float* scores  = (const float*)d_in[0];
    const int*   targets = (const int*)d_in[1];
    float* out = (float*)d_out;

    fused_kernel<<<GRID, TPB>>>(scores, targets, out);
}